// round 7
// baseline (speedup 1.0000x reference)
#include <cuda_runtime.h>
#include <float.h>

#define S    8192
#define D    1024
#define E    64
#define CAP  256
#define NTILE 256   /* S/32 : tiles for rank/scan */
#define NBLK  128   /* S/64 : gate blocks          */

static const size_t OFF_CW  = 1ULL;
static const size_t OFF_DM  = 1ULL + 134217728ULL;   /* 134217729 */
static const size_t OFF_EXP = 1ULL + 268435456ULL;   /* 268435457 */
static const size_t OFF_ORG = 268435521ULL;          /* OFF_EXP + 64 */

/* ---------------- scratch (device globals; no allocs) ---------------- */
__device__ int   d_idx1[S];
__device__ int   d_idx2[S];
__device__ float d_g1[S];
__device__ float d_g2[S];
__device__ int   d_cnt1[NTILE * E];
__device__ int   d_cnt2[NTILE * E];
__device__ int   d_off1[NTILE * E];
__device__ int   d_off2[NTILE * E];
__device__ int   d_total1[E];
__device__ float d_mepart[NBLK * E];

/* ============ kernel 1: gate GEMM + softmax + top-2 =================== */
#define TB 64   /* tokens per gate block */
#define KC 32   /* K chunk */

__global__ __launch_bounds__(256) void gate_kernel(
    const float* __restrict__ x, const float* __restrict__ wg,
    float* __restrict__ out)
{
    /* overlay: xs[64][32] = sbuf[0..2048), ws[32][64] = sbuf[2048..4096),
       ls[64][64] overlays sbuf[0..4096) AFTER the gemm loop finishes. */
    __shared__ float sbuf[4096];
    __shared__ float me_w[8][E];
    __shared__ int   cnt1_s[2][E];
    __shared__ int   cnt2_s[2][E];

    const int tid = threadIdx.x;

    float (*xs)[KC] = reinterpret_cast<float (*)[KC]>(sbuf);          /* [64][32] */
    float (*ws)[E]  = reinterpret_cast<float (*)[E]>(sbuf + 2048);    /* [32][64] */
    float (*ls)[E]  = reinterpret_cast<float (*)[E]>(sbuf);           /* [64][64] */

    float* __restrict__ org = out + OFF_ORG;
    const int blk = blockIdx.x;
    const int s0  = blk * TB;

    if (tid < E) {
        cnt1_s[0][tid] = 0; cnt1_s[1][tid] = 0;
        cnt2_s[0][tid] = 0; cnt2_s[1][tid] = 0;
    }

    const int tx = tid & 15;   /* expert group: experts tx*4 .. tx*4+3 */
    const int ty = tid >> 4;   /* token  group: tokens  ty*4 .. ty*4+3 */

    float acc[4][4];
#pragma unroll
    for (int i = 0; i < 4; i++)
#pragma unroll
        for (int j = 0; j < 4; j++) acc[i][j] = 0.f;

    for (int k0 = 0; k0 < D; k0 += KC) {
        __syncthreads();
#pragma unroll
        for (int j = 0; j < 2; j++) {          /* 64x32 x-tile via float4, streaming */
            int i  = tid + j * 256;            /* float4 index 0..511 */
            int t  = i >> 3, k4 = (i & 7) * 4;
            float4 v = __ldcs(reinterpret_cast<const float4*>(
                             x + (size_t)(s0 + t) * D + k0 + k4));
            *reinterpret_cast<float4*>(&xs[t][k4]) = v;
        }
#pragma unroll
        for (int j = 0; j < 2; j++) {          /* 32x64 w-tile via float4 */
            int i  = tid + j * 256;            /* float4 index 0..511 */
            int k  = i >> 4, e4 = (i & 15) * 4;
            float4 v = *reinterpret_cast<const float4*>(
                             wg + (size_t)(k0 + k) * E + e4);
            *reinterpret_cast<float4*>(&ws[k][e4]) = v;
        }
        __syncthreads();
#pragma unroll
        for (int k = 0; k < KC; k += 4) {
            float xv[4][4], wv[4][4];
#pragma unroll
            for (int i = 0; i < 4; i++) {
                float4 t4 = *reinterpret_cast<const float4*>(&xs[ty * 4 + i][k]);
                xv[i][0] = t4.x; xv[i][1] = t4.y; xv[i][2] = t4.z; xv[i][3] = t4.w;
            }
#pragma unroll
            for (int kk = 0; kk < 4; kk++) {
                float4 t4 = *reinterpret_cast<const float4*>(&ws[k + kk][tx * 4]);
                wv[kk][0] = t4.x; wv[kk][1] = t4.y; wv[kk][2] = t4.z; wv[kk][3] = t4.w;
            }
#pragma unroll
            for (int i = 0; i < 4; i++)
#pragma unroll
                for (int j = 0; j < 4; j++)
#pragma unroll
                    for (int kk = 0; kk < 4; kk++)
                        acc[i][j] += xv[i][kk] * wv[kk][j];
        }
    }

    /* logits -> smem (overlay; all xs/ws reads are done) */
    __syncthreads();
#pragma unroll
    for (int i = 0; i < 4; i++) {
        float4 t4 = make_float4(acc[i][0], acc[i][1], acc[i][2], acc[i][3]);
        *reinterpret_cast<float4*>(&ls[ty * 4 + i][tx * 4]) = t4;
    }
    __syncthreads();

    /* softmax + top-2: warp w handles tokens w*8 .. w*8+7 */
    const int lane = tid & 31;
    const int warp = tid >> 5;
    const unsigned FULL = 0xffffffffu;
    float me0 = 0.f, me1 = 0.f;

    for (int tt = 0; tt < 8; tt++) {
        int t = warp * 8 + tt;
        float v0 = ls[t][lane];
        float v1 = ls[t][lane + 32];

        /* argmax with first-index tie-break */
        float m; int mi;
        if (v1 > v0) { m = v1; mi = lane + 32; } else { m = v0; mi = lane; }
#pragma unroll
        for (int off = 16; off; off >>= 1) {
            float om = __shfl_xor_sync(FULL, m, off);
            int  omi = __shfl_xor_sync(FULL, mi, off);
            if (om > m || (om == m && omi < mi)) { m = om; mi = omi; }
        }
        int idx1 = mi; float mx = m;

        float e0 = __expf(v0 - mx), e1 = __expf(v1 - mx);
        float sum = e0 + e1;
#pragma unroll
        for (int off = 16; off; off >>= 1) sum += __shfl_xor_sync(FULL, sum, off);
        float inv = 1.f / sum;
        float g0 = e0 * inv, g1 = e1 * inv;

        int sg = s0 + t;
        org[(size_t)sg * E + lane]      = g0;
        org[(size_t)sg * E + lane + 32] = g1;
        me0 += g0; me1 += g1;

        /* second argmax excluding idx1 */
        float u0 = (lane == idx1)      ? -FLT_MAX : v0;
        float u1 = (lane + 32 == idx1) ? -FLT_MAX : v1;
        if (u1 > u0) { m = u1; mi = lane + 32; } else { m = u0; mi = lane; }
#pragma unroll
        for (int off = 16; off; off >>= 1) {
            float om = __shfl_xor_sync(FULL, m, off);
            int  omi = __shfl_xor_sync(FULL, mi, off);
            if (om > m || (om == m && omi < mi)) { m = om; mi = omi; }
        }
        int idx2 = mi;

        float c1  = (idx1 < 32) ? g0 : g1;
        float gt1 = __shfl_sync(FULL, c1, idx1 & 31);
        float c2  = (idx2 < 32) ? g0 : g1;
        float gt2 = __shfl_sync(FULL, c2, idx2 & 31);

        if (lane == 0) {
            d_idx1[sg] = idx1; d_idx2[sg] = idx2;
            d_g1[sg] = gt1;    d_g2[sg] = gt2;
            int half = t >> 5;
            atomicAdd(&cnt1_s[half][idx1], 1);
            atomicAdd(&cnt2_s[half][idx2], 1);
        }
    }
    me_w[warp][lane]      = me0;
    me_w[warp][lane + 32] = me1;
    __syncthreads();

    if (tid < E) {
        float s = 0.f;
#pragma unroll
        for (int w = 0; w < 8; w++) s += me_w[w][tid];
        d_mepart[blk * E + tid] = s;
        d_cnt1[(blk * 2 + 0) * E + tid] = cnt1_s[0][tid];
        d_cnt1[(blk * 2 + 1) * E + tid] = cnt1_s[1][tid];
        d_cnt2[(blk * 2 + 0) * E + tid] = cnt2_s[0][tid];
        d_cnt2[(blk * 2 + 1) * E + tid] = cnt2_s[1][tid];
    }
}

/* ---------------- kernel 2: per-expert scan over tiles ---------------- */
__global__ void scan_kernel(float* __restrict__ out) {
    const int e = threadIdx.x;   /* 64 threads */
    int run1 = 0, run2 = 0;
    for (int t0 = 0; t0 < NTILE; t0 += 16) {
        int c1[16], c2[16];
#pragma unroll
        for (int j = 0; j < 16; j++) {
            c1[j] = d_cnt1[(t0 + j) * E + e];
            c2[j] = d_cnt2[(t0 + j) * E + e];
        }
#pragma unroll
        for (int j = 0; j < 16; j++) {
            d_off1[(t0 + j) * E + e] = run1; run1 += c1[j];
            d_off2[(t0 + j) * E + e] = run2; run2 += c2[j];
        }
    }
    d_total1[e] = run1;
    out[OFF_EXP + e] = (float)(run1 + run2);

    float mesum = 0.f;
    for (int b0 = 0; b0 < NBLK; b0 += 16) {
        float mv[16];
#pragma unroll
        for (int j = 0; j < 16; j++) mv[j] = d_mepart[(b0 + j) * E + e];
#pragma unroll
        for (int j = 0; j < 16; j++) mesum += mv[j];
    }
    float p = (mesum / 8192.f) * ((float)run1 / 8192.f);
    __shared__ float red[2];
#pragma unroll
    for (int off = 16; off; off >>= 1) p += __shfl_xor_sync(0xffffffffu, p, off);
    if ((e & 31) == 0) red[e >> 5] = p;
    __syncthreads();
    if (e == 0) out[0] = (red[0] + red[1]) * 4096.f;   /* * E*E */
}

/* ---------------- kernel 3: rank + drop + renorm + scatter ------------ */
__global__ __launch_bounds__(256) void scatter_kernel(
    float* __restrict__ cw, float* __restrict__ dm)
{
    const int lane = threadIdx.x & 31;
    const int warp = threadIdx.x >> 5;
    const int tile = blockIdx.x * 8 + warp;   /* 32 blocks x 8 warps = 256 tiles */
    const int s = tile * 32 + lane;
    const unsigned FULL = 0xffffffffu;
    const unsigned ltmask = (1u << lane) - 1u;

    int e1 = d_idx1[s], e2 = d_idx2[s];
    unsigned mm1 = __match_any_sync(FULL, e1);
    int loc1 = d_off1[tile * E + e1] + __popc(mm1 & ltmask);
    unsigned mm2 = __match_any_sync(FULL, e2);
    int loc2 = d_off2[tile * E + e2] + __popc(mm2 & ltmask) + d_total1[e2];

    bool k1 = loc1 < CAP, k2 = loc2 < CAP;
    float g1 = k1 ? d_g1[s] : 0.f;
    float g2 = k2 ? d_g2[s] : 0.f;
    float denom = fmaxf(g1 + g2, 1.1920929e-07f);   /* float32 eps */
    float w1 = g1 / denom, w2 = g2 / denom;

    if (k1) {
        size_t o = (size_t)s * (E * CAP) + (size_t)e1 * CAP + loc1;
        cw[o] = w1; dm[o] = (w1 != 0.f) ? 1.f : 0.f;
    }
    if (k2) {
        size_t o = (size_t)s * (E * CAP) + (size_t)e2 * CAP + loc2;
        cw[o] = w2; dm[o] = (w2 != 0.f) ? 1.f : 0.f;
    }
}

/* ---------------- launch: fork-join overlap of memset and gate -------- */
extern "C" void kernel_launch(void* const* d_in, const int* in_sizes, int n_in,
                              void* d_out, int out_size) {
    const float* x  = (const float*)d_in[0];
    const float* wg = (const float*)d_in[1];
    float* out = (float*)d_out;

    /* host-side objects, created once; no device memory involved */
    static cudaStream_t s1 = nullptr;
    static cudaEvent_t  e_fork = nullptr, e_join = nullptr;
    if (s1 == nullptr) {
        cudaStreamCreateWithFlags(&s1, cudaStreamNonBlocking);
        cudaEventCreateWithFlags(&e_fork, cudaEventDisableTiming);
        cudaEventCreateWithFlags(&e_join, cudaEventDisableTiming);
    }

    /* fork: side stream zeroes the 1 GiB combine+dispatch region while the
       main stream runs gate + scan (disjoint output regions). */
    cudaEventRecord(e_fork, 0);
    cudaStreamWaitEvent(s1, e_fork, 0);
    cudaMemsetAsync(out + 1, 0, 268435456ULL * sizeof(float), s1);  /* [1, 268435457) */

    gate_kernel<<<NBLK, 256>>>(x, wg, out);
    scan_kernel<<<1, 64>>>(out);

    /* join: scatter needs both the zeroed region and the scan results */
    cudaEventRecord(e_join, s1);
    cudaStreamWaitEvent(0, e_join, 0);
    scatter_kernel<<<32, 256>>>(out + OFF_CW, out + OFF_DM);
}

// round 8
// speedup vs baseline: 1.3314x; 1.3314x over previous
#include <cuda_runtime.h>
#include <float.h>

#define S    8192
#define D    1024
#define E    64
#define CAP  256
#define NTILE 256    /* S/32 tiles for rank/scan  */
#define NBLK  128    /* gate blocks               */
#define FBLK  8192   /* fill blocks               */
#define SCANB 128    /* scan block id             */
#define SCAT0 129    /* first scatter block       */
#define NSCAT 32     /* scatter blocks            */
#define FILL0 161    /* first fill block          */
#define TOTBLK (FILL0 + FBLK)   /* 8353 */

static const size_t OFF_CW  = 1ULL;
static const size_t OFF_DM  = 1ULL + 134217728ULL;   /* 134217729 */
static const size_t OFF_EXP = 1ULL + 268435456ULL;   /* 268435457 */
static const size_t OFF_ORG = 268435521ULL;          /* OFF_EXP + 64 */

/* ---------------- scratch (device globals; no allocs) ---------------- */
__device__ int   d_idx1[S];
__device__ int   d_idx2[S];
__device__ float d_g1[S];
__device__ float d_g2[S];
__device__ int   d_cnt1[NTILE * E];
__device__ int   d_cnt2[NTILE * E];
__device__ int   d_off1[NTILE * E];
__device__ int   d_off2[NTILE * E];
__device__ int   d_total1[E];
__device__ int   d_expc[E];
__device__ float d_mepart[NBLK * E];
/* sync state: zero-initialized at load; self-reset by last exiting block */
__device__ int   g_gate_done;
__device__ int   g_scan_flag;
__device__ int   g_fill_done;
__device__ int   g_all_done;

#define TB 64   /* tokens per gate block */
#define KC 32   /* K chunk */

__global__ __launch_bounds__(256) void mega_kernel(
    const float* __restrict__ x, const float* __restrict__ wg,
    float* __restrict__ out)
{
    /* overlay: xs[64][32]=sbuf[0..2048), ws[32][64]=sbuf[2048..4096),
       ls[64][64] overlays sbuf after the gemm loop. */
    __shared__ float sbuf[4096];
    __shared__ float me_w[8][E];
    __shared__ int   cnt1_s[2][E];
    __shared__ int   cnt2_s[2][E];
    __shared__ float red2[2];

    const int b   = blockIdx.x;
    const int tid = threadIdx.x;

    if (b >= FILL0) {
        /* ================= FILL =====================================
           Block fb zeroes float4s [fb*8192,(fb+1)*8192) of region at
           out+4: floats [4, 268435460). 3-float spill into
           exp_counts[0..2] is rewritten by the scatter phase later. */
        const int fb = b - FILL0;
        float4* p = reinterpret_cast<float4*>(out + 4) + (size_t)fb * 8192 + tid;
        const float4 z = make_float4(0.f, 0.f, 0.f, 0.f);
#pragma unroll
        for (int k = 0; k < 32; k++) p[k * 256] = z;
        __syncthreads();
        if (tid == 0) { __threadfence(); atomicAdd(&g_fill_done, 1); }
    }
    else if (b < NBLK) {
        /* ================= GATE ===================================== */
        float (*xs)[KC] = reinterpret_cast<float (*)[KC]>(sbuf);
        float (*ws)[E]  = reinterpret_cast<float (*)[E]>(sbuf + 2048);
        float (*ls)[E]  = reinterpret_cast<float (*)[E]>(sbuf);

        float* __restrict__ org = out + OFF_ORG;
        const int s0 = b * TB;

        if (tid < E) {
            cnt1_s[0][tid] = 0; cnt1_s[1][tid] = 0;
            cnt2_s[0][tid] = 0; cnt2_s[1][tid] = 0;
        }

        const int tx = tid & 15;
        const int ty = tid >> 4;

        float acc[4][4];
#pragma unroll
        for (int i = 0; i < 4; i++)
#pragma unroll
            for (int j = 0; j < 4; j++) acc[i][j] = 0.f;

        for (int k0 = 0; k0 < D; k0 += KC) {
            __syncthreads();
#pragma unroll
            for (int j = 0; j < 2; j++) {
                int i  = tid + j * 256;
                int t  = i >> 3, k4 = (i & 7) * 4;
                float4 v = __ldcs(reinterpret_cast<const float4*>(
                                 x + (size_t)(s0 + t) * D + k0 + k4));
                *reinterpret_cast<float4*>(&xs[t][k4]) = v;
            }
#pragma unroll
            for (int j = 0; j < 2; j++) {
                int i  = tid + j * 256;
                int k  = i >> 4, e4 = (i & 15) * 4;
                float4 v = *reinterpret_cast<const float4*>(
                                 wg + (size_t)(k0 + k) * E + e4);
                *reinterpret_cast<float4*>(&ws[k][e4]) = v;
            }
            __syncthreads();
#pragma unroll
            for (int k = 0; k < KC; k += 4) {
                float xv[4][4], wv[4][4];
#pragma unroll
                for (int i = 0; i < 4; i++) {
                    float4 t4 = *reinterpret_cast<const float4*>(&xs[ty * 4 + i][k]);
                    xv[i][0] = t4.x; xv[i][1] = t4.y; xv[i][2] = t4.z; xv[i][3] = t4.w;
                }
#pragma unroll
                for (int kk = 0; kk < 4; kk++) {
                    float4 t4 = *reinterpret_cast<const float4*>(&ws[k + kk][tx * 4]);
                    wv[kk][0] = t4.x; wv[kk][1] = t4.y; wv[kk][2] = t4.z; wv[kk][3] = t4.w;
                }
#pragma unroll
                for (int i = 0; i < 4; i++)
#pragma unroll
                    for (int j = 0; j < 4; j++)
#pragma unroll
                        for (int kk = 0; kk < 4; kk++)
                            acc[i][j] += xv[i][kk] * wv[kk][j];
            }
        }

        __syncthreads();
#pragma unroll
        for (int i = 0; i < 4; i++) {
            float4 t4 = make_float4(acc[i][0], acc[i][1], acc[i][2], acc[i][3]);
            *reinterpret_cast<float4*>(&ls[ty * 4 + i][tx * 4]) = t4;
        }
        __syncthreads();

        const int lane = tid & 31;
        const int warp = tid >> 5;
        const unsigned FULL = 0xffffffffu;
        float me0 = 0.f, me1 = 0.f;

        for (int tt = 0; tt < 8; tt++) {
            int t = warp * 8 + tt;
            float v0 = ls[t][lane];
            float v1 = ls[t][lane + 32];

            float m; int mi;
            if (v1 > v0) { m = v1; mi = lane + 32; } else { m = v0; mi = lane; }
#pragma unroll
            for (int off = 16; off; off >>= 1) {
                float om = __shfl_xor_sync(FULL, m, off);
                int  omi = __shfl_xor_sync(FULL, mi, off);
                if (om > m || (om == m && omi < mi)) { m = om; mi = omi; }
            }
            int idx1 = mi; float mx = m;

            float e0 = __expf(v0 - mx), e1 = __expf(v1 - mx);
            float sum = e0 + e1;
#pragma unroll
            for (int off = 16; off; off >>= 1) sum += __shfl_xor_sync(FULL, sum, off);
            float inv = 1.f / sum;
            float g0 = e0 * inv, g1 = e1 * inv;

            int sg = s0 + t;
            org[(size_t)sg * E + lane]      = g0;
            org[(size_t)sg * E + lane + 32] = g1;
            me0 += g0; me1 += g1;

            float u0 = (lane == idx1)      ? -FLT_MAX : v0;
            float u1 = (lane + 32 == idx1) ? -FLT_MAX : v1;
            if (u1 > u0) { m = u1; mi = lane + 32; } else { m = u0; mi = lane; }
#pragma unroll
            for (int off = 16; off; off >>= 1) {
                float om = __shfl_xor_sync(FULL, m, off);
                int  omi = __shfl_xor_sync(FULL, mi, off);
                if (om > m || (om == m && omi < mi)) { m = om; mi = omi; }
            }
            int idx2 = mi;

            float c1  = (idx1 < 32) ? g0 : g1;
            float gt1 = __shfl_sync(FULL, c1, idx1 & 31);
            float c2  = (idx2 < 32) ? g0 : g1;
            float gt2 = __shfl_sync(FULL, c2, idx2 & 31);

            if (lane == 0) {
                d_idx1[sg] = idx1; d_idx2[sg] = idx2;
                d_g1[sg] = gt1;    d_g2[sg] = gt2;
                int half = t >> 5;
                atomicAdd(&cnt1_s[half][idx1], 1);
                atomicAdd(&cnt2_s[half][idx2], 1);
            }
        }
        me_w[warp][lane]      = me0;
        me_w[warp][lane + 32] = me1;
        __syncthreads();

        if (tid < E) {
            float sm = 0.f;
#pragma unroll
            for (int w = 0; w < 8; w++) sm += me_w[w][tid];
            d_mepart[b * E + tid] = sm;
            d_cnt1[(b * 2 + 0) * E + tid] = cnt1_s[0][tid];
            d_cnt1[(b * 2 + 1) * E + tid] = cnt1_s[1][tid];
            d_cnt2[(b * 2 + 0) * E + tid] = cnt2_s[0][tid];
            d_cnt2[(b * 2 + 1) * E + tid] = cnt2_s[1][tid];
        }
        __syncthreads();
        if (tid == 0) { __threadfence(); atomicAdd(&g_gate_done, 1); }
    }
    else if (b == SCANB) {
        /* ================= SCAN (spins on gate) ===================== */
        if (tid == 0) {
            while (atomicAdd(&g_gate_done, 0) < NBLK) __nanosleep(64);
        }
        __syncthreads();
        __threadfence();

        if (tid < E) {
            const int e = tid;
            int run1 = 0, run2 = 0;
            for (int t0 = 0; t0 < NTILE; t0 += 16) {
                int c1[16], c2[16];
#pragma unroll
                for (int j = 0; j < 16; j++) {
                    c1[j] = __ldcg(&d_cnt1[(t0 + j) * E + e]);
                    c2[j] = __ldcg(&d_cnt2[(t0 + j) * E + e]);
                }
#pragma unroll
                for (int j = 0; j < 16; j++) {
                    d_off1[(t0 + j) * E + e] = run1; run1 += c1[j];
                    d_off2[(t0 + j) * E + e] = run2; run2 += c2[j];
                }
            }
            d_total1[e] = run1;
            d_expc[e]   = run1 + run2;

            float mesum = 0.f;
            for (int b0 = 0; b0 < NBLK; b0 += 16) {
                float mv[16];
#pragma unroll
                for (int j = 0; j < 16; j++) mv[j] = __ldcg(&d_mepart[(b0 + j) * E + e]);
#pragma unroll
                for (int j = 0; j < 16; j++) mesum += mv[j];
            }
            float p = (mesum / 8192.f) * ((float)run1 / 8192.f);
#pragma unroll
            for (int off = 16; off; off >>= 1)
                p += __shfl_xor_sync(0xffffffffu, p, off);
            if ((e & 31) == 0) red2[e >> 5] = p;
        }
        __syncthreads();
        if (tid == 0) {
            out[0] = (red2[0] + red2[1]) * 4096.f;   /* l_aux * E*E */
            out[1] = 0.f; out[2] = 0.f; out[3] = 0.f;
            __threadfence();
            atomicExch(&g_scan_flag, 1);
        }
    }
    else {
        /* ================= SCATTER (spins on fill+scan) ============= */
        const int sb = b - SCAT0;
        if (tid == 0) {
            while (atomicAdd(&g_fill_done, 0) < FBLK) __nanosleep(128);
            while (atomicAdd(&g_scan_flag, 0) == 0)   __nanosleep(64);
        }
        __syncthreads();
        __threadfence();

        float* __restrict__ cw = out + OFF_CW;
        float* __restrict__ dm = out + OFF_DM;

        const int lane = tid & 31;
        const int warp = tid >> 5;
        const int tile = sb * 8 + warp;   /* 32 blocks x 8 warps = 256 tiles */
        const int s = tile * 32 + lane;
        const unsigned FULL = 0xffffffffu;
        const unsigned ltmask = (1u << lane) - 1u;

        int e1 = __ldcg(&d_idx1[s]), e2 = __ldcg(&d_idx2[s]);
        unsigned mm1 = __match_any_sync(FULL, e1);
        int loc1 = __ldcg(&d_off1[tile * E + e1]) + __popc(mm1 & ltmask);
        unsigned mm2 = __match_any_sync(FULL, e2);
        int loc2 = __ldcg(&d_off2[tile * E + e2]) + __popc(mm2 & ltmask)
                 + __ldcg(&d_total1[e2]);

        bool k1 = loc1 < CAP, k2 = loc2 < CAP;
        float g1 = k1 ? __ldcg(&d_g1[s]) : 0.f;
        float g2 = k2 ? __ldcg(&d_g2[s]) : 0.f;
        float denom = fmaxf(g1 + g2, 1.1920929e-07f);   /* fp32 eps */
        float w1 = g1 / denom, w2 = g2 / denom;

        if (k1) {
            size_t o = (size_t)s * (E * CAP) + (size_t)e1 * CAP + loc1;
            cw[o] = w1; dm[o] = (w1 != 0.f) ? 1.f : 0.f;
        }
        if (k2) {
            size_t o = (size_t)s * (E * CAP) + (size_t)e2 * CAP + loc2;
            cw[o] = w2; dm[o] = (w2 != 0.f) ? 1.f : 0.f;
        }
        /* rewrite exp_counts (fill spill zeroed exp[0..2]) */
        if (sb == 0 && tid < E)
            out[OFF_EXP + tid] = (float)__ldcg(&d_expc[tid]);
    }

    /* ========== epilogue: last exiting block resets sync state ======= */
    __syncthreads();
    if (tid == 0) {
        if (atomicAdd(&g_all_done, 1) == TOTBLK - 1) {
            atomicExch(&g_gate_done, 0);
            atomicExch(&g_scan_flag, 0);
            atomicExch(&g_fill_done, 0);
            atomicExch(&g_all_done, 0);
        }
    }
}

/* ---------------- launch: ONE kernel ---------------------------------- */
extern "C" void kernel_launch(void* const* d_in, const int* in_sizes, int n_in,
                              void* d_out, int out_size) {
    const float* x  = (const float*)d_in[0];
    const float* wg = (const float*)d_in[1];
    float* out = (float*)d_out;
    mega_kernel<<<TOTBLK, 256>>>(x, wg, out);
}

// round 12
// speedup vs baseline: 1.3430x; 1.0088x over previous
#include <cuda_runtime.h>
#include <float.h>

#define S    8192
#define D    1024
#define E    64
#define CAP  256
#define NTILE 256    /* S/32 tiles for rank/scan  */
#define NBLK  128    /* gate blocks               */
#define FBLK  4096   /* fill blocks (256KB each)  */
#define SCANB 128    /* scan block id             */
#define SCAT0 129    /* first scatter block       */
#define NSCAT 32     /* scatter blocks            */
#define FILL0 161    /* first fill block          */
#define TOTBLK (FILL0 + FBLK)   /* 4257 */

static const size_t OFF_CW  = 1ULL;
static const size_t OFF_DM  = 1ULL + 134217728ULL;   /* 134217729 */
static const size_t OFF_EXP = 1ULL + 268435456ULL;   /* 268435457 */
static const size_t OFF_ORG = 268435521ULL;          /* OFF_EXP + 64 */

/* ---------------- scratch (device globals; no allocs) ---------------- */
__device__ int   d_idx1[S];
__device__ int   d_idx2[S];
__device__ float d_g1[S];
__device__ float d_g2[S];
__device__ int   d_cnt1[NTILE * E];
__device__ int   d_cnt2[NTILE * E];
__device__ int   d_off1[NTILE * E];
__device__ int   d_off2[NTILE * E];
__device__ int   d_total1[E];
__device__ int   d_expc[E];
__device__ float d_mepart[NBLK * E];
/* sync state: zero-initialized at load; self-reset by last exiting block */
__device__ int   g_gate_done;
__device__ int   g_scan_flag;
__device__ int   g_fill_done;
__device__ int   g_all_done;

#define TB 64   /* tokens per gate block */
#define KC 32   /* K chunk */

__global__ __launch_bounds__(256) void mega_kernel(
    const float* __restrict__ x, const float* __restrict__ wg,
    float* __restrict__ out)
{
    /* overlay: xs[64][32]=sbuf[0..2048), ws[32][64]=sbuf[2048..4096),
       ls[64][64] overlays sbuf after the gemm loop. */
    __shared__ float sbuf[4096];
    __shared__ float me_w[8][E];
    __shared__ int   cnt1_s[2][E];
    __shared__ int   cnt2_s[2][E];
    __shared__ float red2[2];

    const int b   = blockIdx.x;
    const int tid = threadIdx.x;

    if (b >= FILL0) {
        /* ================= FILL (STG.256) ===========================
           v8.f32 region covers floats [8, 8 + 4096*8192*8) =
           [8, 268435464). Block fb owns float8s [fb*8192,(fb+1)*8192)
           (256 KB contiguous). Base out+8 is 32B-aligned. The 7-float
           spill into exp_counts[0..6] is rewritten by the scatter
           phase after fill completes. Floats 1..7 are zeroed scalar. */
        const int fb = b - FILL0;
        float* base = out + 8 + ((size_t)fb * 8192 + tid) * 8;
        const float z = 0.f;
#pragma unroll
        for (int k = 0; k < 32; k++) {
            asm volatile(
                "st.global.v8.f32 [%0], {%1,%2,%3,%4,%5,%6,%7,%8};"
                :: "l"(base + (size_t)k * 2048),
                   "f"(z), "f"(z), "f"(z), "f"(z),
                   "f"(z), "f"(z), "f"(z), "f"(z)
                : "memory");
        }
        if (fb == 0 && tid >= 1 && tid < 8) out[tid] = 0.f;
        __syncthreads();
        if (tid == 0) { __threadfence(); atomicAdd(&g_fill_done, 1); }
    }
    else if (b < NBLK) {
        /* ================= GATE ===================================== */
        float (*xs)[KC] = reinterpret_cast<float (*)[KC]>(sbuf);
        float (*ws)[E]  = reinterpret_cast<float (*)[E]>(sbuf + 2048);
        float (*ls)[E]  = reinterpret_cast<float (*)[E]>(sbuf);

        float* __restrict__ org = out + OFF_ORG;
        const int s0 = b * TB;

        if (tid < E) {
            cnt1_s[0][tid] = 0; cnt1_s[1][tid] = 0;
            cnt2_s[0][tid] = 0; cnt2_s[1][tid] = 0;
        }

        const int tx = tid & 15;
        const int ty = tid >> 4;

        float acc[4][4];
#pragma unroll
        for (int i = 0; i < 4; i++)
#pragma unroll
            for (int j = 0; j < 4; j++) acc[i][j] = 0.f;

        for (int k0 = 0; k0 < D; k0 += KC) {
            __syncthreads();
#pragma unroll
            for (int j = 0; j < 2; j++) {
                int i  = tid + j * 256;
                int t  = i >> 3, k4 = (i & 7) * 4;
                float4 v = __ldcs(reinterpret_cast<const float4*>(
                                 x + (size_t)(s0 + t) * D + k0 + k4));
                *reinterpret_cast<float4*>(&xs[t][k4]) = v;
            }
#pragma unroll
            for (int j = 0; j < 2; j++) {
                int i  = tid + j * 256;
                int k  = i >> 4, e4 = (i & 15) * 4;
                float4 v = *reinterpret_cast<const float4*>(
                                 wg + (size_t)(k0 + k) * E + e4);
                *reinterpret_cast<float4*>(&ws[k][e4]) = v;
            }
            __syncthreads();
#pragma unroll
            for (int k = 0; k < KC; k += 4) {
                float xv[4][4], wv[4][4];
#pragma unroll
                for (int i = 0; i < 4; i++) {
                    float4 t4 = *reinterpret_cast<const float4*>(&xs[ty * 4 + i][k]);
                    xv[i][0] = t4.x; xv[i][1] = t4.y; xv[i][2] = t4.z; xv[i][3] = t4.w;
                }
#pragma unroll
                for (int kk = 0; kk < 4; kk++) {
                    float4 t4 = *reinterpret_cast<const float4*>(&ws[k + kk][tx * 4]);
                    wv[kk][0] = t4.x; wv[kk][1] = t4.y; wv[kk][2] = t4.z; wv[kk][3] = t4.w;
                }
#pragma unroll
                for (int i = 0; i < 4; i++)
#pragma unroll
                    for (int j = 0; j < 4; j++)
#pragma unroll
                        for (int kk = 0; kk < 4; kk++)
                            acc[i][j] += xv[i][kk] * wv[kk][j];
            }
        }

        __syncthreads();
#pragma unroll
        for (int i = 0; i < 4; i++) {
            float4 t4 = make_float4(acc[i][0], acc[i][1], acc[i][2], acc[i][3]);
            *reinterpret_cast<float4*>(&ls[ty * 4 + i][tx * 4]) = t4;
        }
        __syncthreads();

        const int lane = tid & 31;
        const int warp = tid >> 5;
        const unsigned FULL = 0xffffffffu;
        float me0 = 0.f, me1 = 0.f;

        for (int tt = 0; tt < 8; tt++) {
            int t = warp * 8 + tt;
            float v0 = ls[t][lane];
            float v1 = ls[t][lane + 32];

            float m; int mi;
            if (v1 > v0) { m = v1; mi = lane + 32; } else { m = v0; mi = lane; }
#pragma unroll
            for (int off = 16; off; off >>= 1) {
                float om = __shfl_xor_sync(FULL, m, off);
                int  omi = __shfl_xor_sync(FULL, mi, off);
                if (om > m || (om == m && omi < mi)) { m = om; mi = omi; }
            }
            int idx1 = mi; float mx = m;

            float e0 = __expf(v0 - mx), e1 = __expf(v1 - mx);
            float sum = e0 + e1;
#pragma unroll
            for (int off = 16; off; off >>= 1) sum += __shfl_xor_sync(FULL, sum, off);
            float inv = 1.f / sum;
            float g0 = e0 * inv, g1 = e1 * inv;

            int sg = s0 + t;
            org[(size_t)sg * E + lane]      = g0;
            org[(size_t)sg * E + lane + 32] = g1;
            me0 += g0; me1 += g1;

            float u0 = (lane == idx1)      ? -FLT_MAX : v0;
            float u1 = (lane + 32 == idx1) ? -FLT_MAX : v1;
            if (u1 > u0) { m = u1; mi = lane + 32; } else { m = u0; mi = lane; }
#pragma unroll
            for (int off = 16; off; off >>= 1) {
                float om = __shfl_xor_sync(FULL, m, off);
                int  omi = __shfl_xor_sync(FULL, mi, off);
                if (om > m || (om == m && omi < mi)) { m = om; mi = omi; }
            }
            int idx2 = mi;

            float c1  = (idx1 < 32) ? g0 : g1;
            float gt1 = __shfl_sync(FULL, c1, idx1 & 31);
            float c2  = (idx2 < 32) ? g0 : g1;
            float gt2 = __shfl_sync(FULL, c2, idx2 & 31);

            if (lane == 0) {
                d_idx1[sg] = idx1; d_idx2[sg] = idx2;
                d_g1[sg] = gt1;    d_g2[sg] = gt2;
                int half = t >> 5;
                atomicAdd(&cnt1_s[half][idx1], 1);
                atomicAdd(&cnt2_s[half][idx2], 1);
            }
        }
        me_w[warp][lane]      = me0;
        me_w[warp][lane + 32] = me1;
        __syncthreads();

        if (tid < E) {
            float sm = 0.f;
#pragma unroll
            for (int w = 0; w < 8; w++) sm += me_w[w][tid];
            d_mepart[b * E + tid] = sm;
            d_cnt1[(b * 2 + 0) * E + tid] = cnt1_s[0][tid];
            d_cnt1[(b * 2 + 1) * E + tid] = cnt1_s[1][tid];
            d_cnt2[(b * 2 + 0) * E + tid] = cnt2_s[0][tid];
            d_cnt2[(b * 2 + 1) * E + tid] = cnt2_s[1][tid];
        }
        __syncthreads();
        if (tid == 0) { __threadfence(); atomicAdd(&g_gate_done, 1); }
    }
    else if (b == SCANB) {
        /* ================= SCAN (spins on gate) ===================== */
        if (tid == 0) {
            while (atomicAdd(&g_gate_done, 0) < NBLK) __nanosleep(64);
        }
        __syncthreads();
        __threadfence();

        if (tid < E) {
            const int e = tid;
            int run1 = 0, run2 = 0;
            for (int t0 = 0; t0 < NTILE; t0 += 16) {
                int c1[16], c2[16];
#pragma unroll
                for (int j = 0; j < 16; j++) {
                    c1[j] = __ldcg(&d_cnt1[(t0 + j) * E + e]);
                    c2[j] = __ldcg(&d_cnt2[(t0 + j) * E + e]);
                }
#pragma unroll
                for (int j = 0; j < 16; j++) {
                    d_off1[(t0 + j) * E + e] = run1; run1 += c1[j];
                    d_off2[(t0 + j) * E + e] = run2; run2 += c2[j];
                }
            }
            d_total1[e] = run1;
            d_expc[e]   = run1 + run2;

            float mesum = 0.f;
            for (int b0 = 0; b0 < NBLK; b0 += 16) {
                float mv[16];
#pragma unroll
                for (int j = 0; j < 16; j++) mv[j] = __ldcg(&d_mepart[(b0 + j) * E + e]);
#pragma unroll
                for (int j = 0; j < 16; j++) mesum += mv[j];
            }
            float p = (mesum / 8192.f) * ((float)run1 / 8192.f);
#pragma unroll
            for (int off = 16; off; off >>= 1)
                p += __shfl_xor_sync(0xffffffffu, p, off);
            if ((e & 31) == 0) red2[e >> 5] = p;
        }
        __syncthreads();
        if (tid == 0) {
            out[0] = (red2[0] + red2[1]) * 4096.f;   /* l_aux * E*E */
            __threadfence();
            atomicExch(&g_scan_flag, 1);
        }
    }
    else {
        /* ================= SCATTER (spins on fill+scan) ============= */
        const int sb = b - SCAT0;
        if (tid == 0) {
            while (atomicAdd(&g_fill_done, 0) < FBLK) __nanosleep(128);
            while (atomicAdd(&g_scan_flag, 0) == 0)   __nanosleep(64);
        }
        __syncthreads();
        __threadfence();

        float* __restrict__ cw = out + OFF_CW;
        float* __restrict__ dm = out + OFF_DM;

        const int lane = tid & 31;
        const int warp = tid >> 5;
        const int tile = sb * 8 + warp;   /* 32 blocks x 8 warps = 256 tiles */
        const int s = tile * 32 + lane;
        const unsigned FULL = 0xffffffffu;
        const unsigned ltmask = (1u << lane) - 1u;

        int e1 = __ldcg(&d_idx1[s]), e2 = __ldcg(&d_idx2[s]);
        unsigned mm1 = __match_any_sync(FULL, e1);
        int loc1 = __ldcg(&d_off1[tile * E + e1]) + __popc(mm1 & ltmask);
        unsigned mm2 = __match_any_sync(FULL, e2);
        int loc2 = __ldcg(&d_off2[tile * E + e2]) + __popc(mm2 & ltmask)
                 + __ldcg(&d_total1[e2]);

        bool k1 = loc1 < CAP, k2 = loc2 < CAP;
        float g1 = k1 ? __ldcg(&d_g1[s]) : 0.f;
        float g2 = k2 ? __ldcg(&d_g2[s]) : 0.f;
        float denom = fmaxf(g1 + g2, 1.1920929e-07f);   /* fp32 eps */
        float w1 = g1 / denom, w2 = g2 / denom;

        if (k1) {
            size_t o = (size_t)s * (E * CAP) + (size_t)e1 * CAP + loc1;
            cw[o] = w1; dm[o] = (w1 != 0.f) ? 1.f : 0.f;
        }
        if (k2) {
            size_t o = (size_t)s * (E * CAP) + (size_t)e2 * CAP + loc2;
            cw[o] = w2; dm[o] = (w2 != 0.f) ? 1.f : 0.f;
        }
        /* rewrite exp_counts (fill spill zeroed exp[0..6]) */
        if (sb == 0 && tid < E)
            out[OFF_EXP + tid] = (float)__ldcg(&d_expc[tid]);
    }

    /* ========== epilogue: last exiting block resets sync state ======= */
    __syncthreads();
    if (tid == 0) {
        if (atomicAdd(&g_all_done, 1) == TOTBLK - 1) {
            atomicExch(&g_gate_done, 0);
            atomicExch(&g_scan_flag, 0);
            atomicExch(&g_fill_done, 0);
            atomicExch(&g_all_done, 0);
        }
    }
}

/* ---------------- launch: ONE kernel ---------------------------------- */
extern "C" void kernel_launch(void* const* d_in, const int* in_sizes, int n_in,
                              void* d_out, int out_size) {
    const float* x  = (const float*)d_in[0];
    const float* wg = (const float*)d_in[1];
    float* out = (float*)d_out;
    mega_kernel<<<TOTBLK, 256>>>(x, wg, out);
}